// round 6
// baseline (speedup 1.0000x reference)
#include <cuda_runtime.h>
#include <math.h>

#define NB   2048
#define NCTA 148
#define NTHR 256
#define TTOT (NCTA * NTHR)

typedef unsigned int       u32;
typedef unsigned long long u64;

// ---------------- static device scratch ----------------
__device__ float  g_bufM[7356416];   // conv/pool outputs, layout [n][lp][c]
__device__ u64    g_bufP[919552];    // packed activations [n][lp]
__device__ float  g_bw1[128];
__device__ float  g_bwfc[1080];
__device__ u32    g_wp2[144];
__device__ u32    g_wp3[288];
__device__ u32    g_wp4[448];
__device__ u64    g_wp5[320];
__device__ u64    g_wp6[192];
__device__ u64    g_wp7[216];
__device__ float  g_scales[320];
__device__ double g_psd1[1184];      // block1 fp64 stat partials [8][148]
__device__ double g_psd2[1184];
__device__ u64    g_sS1[320];        // exact int totals, layers 2-7
__device__ u64    g_sS2[320];
__device__ int    g_barArrive;       // zero-init; restored each run
__device__ int    g_barGen;

__device__ __forceinline__ int popc_w(u32 x) { return __popc(x); }
__device__ __forceinline__ int popc_w(u64 x) { return __popcll(x); }
__device__ __forceinline__ u64 pack2f(float lo, float hi) {
    u64 d; asm("mov.b64 %0,{%1,%2};" : "=l"(d) : "f"(lo), "f"(hi)); return d;
}
__device__ __forceinline__ void unpack2f(u64 v, float& lo, float& hi) {
    asm("mov.b64 {%0,%1},%2;" : "=f"(lo), "=f"(hi) : "l"(v));
}
__device__ __forceinline__ u64 ffma2(u64 a, u64 b, u64 c) {
    u64 d; asm("fma.rn.f32x2 %0,%1,%2,%3;" : "=l"(d) : "l"(a), "l"(b), "l"(c)); return d;
}

// ---------------- software grid barrier (all 148 CTAs resident: grid <= SM count) ----------------
__device__ __forceinline__ void grid_sync()
{
    __syncthreads();
    if (threadIdx.x == 0) {
        __threadfence();
        int gen = atomicAdd(&g_barGen, 0);
        if (atomicAdd(&g_barArrive, 1) == NCTA - 1) {
            g_barArrive = 0;
            __threadfence();
            atomicExch(&g_barGen, gen + 1);
        } else {
            while (atomicAdd(&g_barGen, 0) == gen) __nanosleep(64);
        }
    }
    __syncthreads();
}

// ---------------- weight binarization (separate small node) ----------------
__global__ void binw_all_kernel(
    const float* w1, const float* w2, const float* w3, const float* w4,
    const float* w5, const float* w6, const float* w7, const float* wfc)
{
    const int starts[9] = {0, 8, 20, 52, 116, 180, 244, 316, 321};
    const int CINs[8]   = {1, 8, 12, 32, 64, 64, 64, 216};
    const int Ks[8]     = {16, 12, 9, 7, 5, 3, 3, 1};
    const int soff[8]   = {0, 0, 12, 44, 108, 172, 236, 0};
    const float* ws[8]  = {w1, w2, w3, w4, w5, w6, w7, wfc};

    const int bx = blockIdx.x;
    int layer = 0;
    while (bx >= starts[layer + 1]) layer++;
    const int o   = bx - starts[layer];
    const int CIN = CINs[layer], K = Ks[layer], IK = CIN * K;
    const float* wrow = ws[layer] + o * IK;
    const int tid = threadIdx.x;

    __shared__ double sd[64];
    double acc = 0.0;
    for (int i = tid; i < IK; i += 64) acc += (double)fabsf(wrow[i]);
    sd[tid] = acc;
    __syncthreads();
    for (int s = 32; s > 0; s >>= 1) {
        if (tid < s) sd[tid] += sd[tid + s];
        __syncthreads();
    }
    const float scale = (float)(sd[0] / (double)IK);

    if (layer == 0) {
        for (int i = tid; i < IK; i += 64) {
            float v = wrow[i];
            g_bw1[o * IK + i] = (v > 0.f) ? scale : ((v < 0.f) ? -scale : 0.f);
        }
    } else if (layer == 7) {
        for (int i = tid; i < IK; i += 64) {
            float v = wrow[i];
            g_bwfc[o * IK + i] = (v > 0.f) ? scale : ((v < 0.f) ? -scale : 0.f);
        }
    } else {
        if (tid == 0) g_scales[soff[layer] + o] = scale;
        if (layer <= 3) {
            u32* wp = (layer == 1) ? g_wp2 : (layer == 2) ? g_wp3 : g_wp4;
            for (int k = tid; k < K; k += 64) {
                u32 word = 0;
                for (int ci = 0; ci < CIN; ci++)
                    if (wrow[ci * K + k] > 0.f) word |= (1u << ci);
                wp[o * K + k] = word;
            }
        } else {
            u64* wp = (layer == 4) ? g_wp5 : (layer == 5) ? g_wp6 : g_wp7;
            for (int k = tid; k < K; k += 64) {
                u64 word = 0;
                for (int ci = 0; ci < CIN; ci++)
                    if (wrow[ci * K + k] > 0.f) word |= (1ull << ci);
                wp[o * K + k] = word;
            }
        }
    }
}

// ---------------- XNOR-popcount conv phase ----------------
template <typename WT, int CIN, int COUT, int CB, int K, int STR, int PAD, int PK, int PS, int LIN, int LP>
__device__ void conv_phase(const WT* __restrict__ inP, float* __restrict__ outM,
                           const WT* __restrict__ wp, const float* __restrict__ scales,
                           u64* __restrict__ sT1, u64* __restrict__ sT2,
                           u64* smu, int gtid)
{
    constexpr int WREAL = (PK - 1) * STR + K;
    constexpr WT  MCIN  = (CIN >= (int)(8 * sizeof(WT))) ? (WT)~(WT)0 : (WT)(((WT)1 << CIN) - 1);
    WT*    sw   = (WT*)smu;              // <=2560B
    float* ssc  = (float*)(smu + 320);
    int*   ssum = (int*)(smu + 356);
    int*   ssq  = (int*)(smu + 392);
    const int tid = threadIdx.x;

    for (int i = tid; i < COUT * K; i += NTHR) sw[i] = wp[i];
    if (tid < COUT) { ssc[tid] = scales[tid]; ssum[tid] = 0; ssq[tid] = 0; }
    __syncthreads();

    for (int e = gtid; e < NB * LP; e += TTOT) {
        const int n = e / LP, lp = e - n * LP;
        const int base0 = lp * PS * STR - PAD;
        const WT* __restrict__ ib = inP + (size_t)n * LIN;
        WT win[WREAL], msk[WREAL];
        int cnt[PK];
#pragma unroll
        for (int t = 0; t < WREAL; t++) {
            int p = base0 + t;
            bool v = (p >= 0 && p < LIN);
            win[t] = v ? ib[p] : (WT)0;
            msk[t] = v ? MCIN : (WT)0;
        }
#pragma unroll
        for (int j = 0; j < PK; j++) {
            int cc = 0;
#pragma unroll
            for (int k = 0; k < K; k++) cc += (msk[j * STR + k] != 0) ? CIN : 0;
            cnt[j] = cc;
        }
#pragma unroll 1
        for (int cb = 0; cb < COUT; cb += CB) {
            int acc[CB][PK];
#pragma unroll
            for (int c = 0; c < CB; c++)
#pragma unroll
                for (int j = 0; j < PK; j++) acc[c][j] = 0;
#pragma unroll
            for (int k = 0; k < K; k++) {
#pragma unroll
                for (int c = 0; c < CB; c++) {
                    WT wk = sw[(cb + c) * K + k];
#pragma unroll
                    for (int j = 0; j < PK; j++) {
                        int t = j * STR + k;
                        acc[c][j] += popc_w((WT)(~(win[t] ^ wk) & msk[t]));
                    }
                }
            }
#pragma unroll
            for (int c = 0; c < CB; c++) {
                int m = 2 * acc[c][0] - cnt[0];
#pragma unroll
                for (int j = 1; j < PK; j++) {
                    int s = 2 * acc[c][j] - cnt[j];
                    m = (s > m) ? s : m;
                }
                outM[(size_t)e * COUT + cb + c] = ssc[cb + c] * (float)m;
                atomicAdd(&ssum[cb + c], m);
                atomicAdd(&ssq[cb + c], m * m);
            }
        }
    }
    __syncthreads();
    if (tid < COUT) {
        atomicAdd(&sT1[tid], (u64)(long long)ssum[tid]);
        atomicAdd(&sT2[tid], (u64)(long long)ssq[tid]);
    }
}

// ---------------- BN + sign + pack phase ----------------
template <typename WT, int C, int LP>
__device__ void pack_phase(const float* __restrict__ m, WT* __restrict__ outP,
                           const u64* __restrict__ sT1, const u64* __restrict__ sT2,
                           const float* __restrict__ scales,
                           const float* __restrict__ gamma, const float* __restrict__ beta,
                           double invcnt, u64* smu, int gtid)
{
    float* sa = (float*)smu;
    float* sc = (float*)(smu + 40);
    const int tid = threadIdx.x;
    if (tid < C) {
        double sl  = (double)(long long)sT1[tid];
        double s2  = (double)(long long)sT2[tid];
        double scw = (double)scales[tid];
        double mm  = scw * sl * invcnt;
        double e2  = scw * scw * s2 * invcnt;
        double v   = e2 - mm * mm;
        if (v < 0.0) v = 0.0;
        double a = (double)gamma[tid] / sqrt(v + 1e-5);
        sa[tid] = (float)a;
        sc[tid] = (float)((double)beta[tid] - mm * a);
    }
    __syncthreads();
    for (int e = gtid; e < NB * LP; e += TTOT) {
        const float4* mp = (const float4*)(m + (size_t)e * C);
        WT word = 0;
#pragma unroll
        for (int q = 0; q < C / 4; q++) {
            float4 v = mp[q];
            if (fmaf(sa[4 * q + 0], v.x, sc[4 * q + 0]) > 0.f) word |= ((WT)1 << (4 * q + 0));
            if (fmaf(sa[4 * q + 1], v.y, sc[4 * q + 1]) > 0.f) word |= ((WT)1 << (4 * q + 1));
            if (fmaf(sa[4 * q + 2], v.z, sc[4 * q + 2]) > 0.f) word |= ((WT)1 << (4 * q + 2));
            if (fmaf(sa[4 * q + 3], v.w, sc[4 * q + 3]) > 0.f) word |= ((WT)1 << (4 * q + 3));
        }
        outP[e] = word;
    }
}

// ---------------- persistent mega kernel: conv1 ... FC ----------------
__global__ void __launch_bounds__(NTHR, 1) mega_kernel(
    const float* __restrict__ x,
    const float* __restrict__ g1, const float* __restrict__ b1,
    const float* __restrict__ g2, const float* __restrict__ b2,
    const float* __restrict__ g3, const float* __restrict__ b3,
    const float* __restrict__ g4, const float* __restrict__ b4,
    const float* __restrict__ g5, const float* __restrict__ b5,
    const float* __restrict__ g6, const float* __restrict__ b6,
    const float* __restrict__ g7, const float* __restrict__ b7,
    float* __restrict__ out)
{
    __shared__ u64 smu[1024];   // 8KB phase-union
    const int tid  = threadIdx.x;
    const int gtid = blockIdx.x * NTHR + tid;
    u32* bufP32 = (u32*)g_bufP;

    // ---- phase: zero totals + conv1 (fp32, FFMA2) ----
    {
        for (int i = gtid; i < 320; i += TTOT) { g_sS1[i] = 0; g_sS2[i] = 0; }
        u64*    sw2 = smu;                     // 128 packed weights
        double* sd1 = (double*)(smu + 512);    // [8 warps][8 ch]
        double* sd2 = (double*)(smu + 576);
        if (tid < 128) { float w = g_bw1[tid]; sw2[tid] = pack2f(w, w); }
        __syncthreads();

        float f1[8], f2[8];
#pragma unroll
        for (int c = 0; c < 8; c++) { f1[c] = 0.f; f2[c] = 0.f; }

        for (int e = gtid; e < NB * 225; e += TTOT) {
            const int n = e / 225, slot = e - n * 225;
            const int lp0 = slot * 2;
            const bool v1 = (slot < 224);
            const int base0 = lp0 * 8 - 7;
            const float* __restrict__ xp = x + (size_t)n * 3600;
            float win[38];
#pragma unroll
            for (int t = 0; t < 38; t++) {
                int p = base0 + t;
                win[t] = (p >= 0 && p < 3600) ? __ldg(xp + p) : 0.f;
            }
            u64 pz[36];
#pragma unroll
            for (int t = 0; t < 36; t++) pz[t] = pack2f(win[t], win[t + 2]);

#pragma unroll
            for (int c = 0; c < 8; c++) {
                u64 a0 = 0, a1 = 0, a2 = 0, a3 = 0, a4 = 0, a5 = 0;
#pragma unroll
                for (int k = 0; k < 16; k++) {
                    u64 wk = sw2[c * 16 + k];
                    a0 = ffma2(pz[k],      wk, a0);
                    a1 = ffma2(pz[4 + k],  wk, a1);
                    a2 = ffma2(pz[8 + k],  wk, a2);
                    a3 = ffma2(pz[12 + k], wk, a3);
                    a4 = ffma2(pz[16 + k], wk, a4);
                    a5 = ffma2(pz[20 + k], wk, a5);
                }
                float s0, s1, s2v, s3, s4, s5, s6, s7, s8, s9, s10, s11;
                unpack2f(a0, s0, s1);  unpack2f(a1, s2v, s3); unpack2f(a2, s4, s5);
                unpack2f(a3, s6, s7);  unpack2f(a4, s8, s9);  unpack2f(a5, s10, s11);
                float m0 = fmaxf(fmaxf(fmaxf(s0, s1), fmaxf(s2v, s3)),
                                 fmaxf(fmaxf(s4, s5), fmaxf(s6, s7)));
                float m1 = fmaxf(fmaxf(fmaxf(s4, s5), fmaxf(s6, s7)),
                                 fmaxf(fmaxf(s8, s9), fmaxf(s10, s11)));
                g_bufM[((size_t)n * 449 + lp0) * 8 + c] = m0;
                f1[c] += m0; f2[c] += m0 * m0;
                if (v1) {
                    g_bufM[((size_t)n * 449 + lp0 + 1) * 8 + c] = m1;
                    f1[c] += m1; f2[c] += m1 * m1;
                }
            }
        }
        const int lane = tid & 31, wid = tid >> 5;
#pragma unroll
        for (int c = 0; c < 8; c++) {
            float v1r = f1[c], v2r = f2[c];
#pragma unroll
            for (int off = 16; off > 0; off >>= 1) {
                v1r += __shfl_down_sync(0xFFFFFFFFu, v1r, off);
                v2r += __shfl_down_sync(0xFFFFFFFFu, v2r, off);
            }
            if (lane == 0) { sd1[wid * 8 + c] = (double)v1r; sd2[wid * 8 + c] = (double)v2r; }
        }
        __syncthreads();
        if (tid < 8) {
            double t1 = 0.0, t2 = 0.0;
#pragma unroll
            for (int w = 0; w < 8; w++) { t1 += sd1[w * 8 + tid]; t2 += sd2[w * 8 + tid]; }
            g_psd1[tid * NCTA + blockIdx.x] = t1;
            g_psd2[tid * NCTA + blockIdx.x] = t2;
        }
    }
    grid_sync();

    // ---- phase: pack1 (block1 BN coefs from fp64 partials, fixed order) ----
    {
        float* sa = (float*)smu;
        float* sc = (float*)(smu + 40);
        if (tid < 8) {
            double t1 = 0.0, t2 = 0.0;
#pragma unroll 1
            for (int i = 0; i < NCTA; i++) { t1 += g_psd1[tid * NCTA + i]; t2 += g_psd2[tid * NCTA + i]; }
            const double invcnt = 1.0 / (2048.0 * 449.0);
            double m = t1 * invcnt;
            double v = t2 * invcnt - m * m;
            if (v < 0.0) v = 0.0;
            double a = (double)g1[tid] / sqrt(v + 1e-5);
            sa[tid] = (float)a;
            sc[tid] = (float)((double)b1[tid] - m * a);
        }
        __syncthreads();
        for (int e = gtid; e < NB * 449; e += TTOT) {
            const float4* mp = (const float4*)(g_bufM + (size_t)e * 8);
            float4 v0 = mp[0], v1 = mp[1];
            u32 w = 0;
            if (fmaf(sa[0], v0.x, sc[0]) > 0.f) w |= 1u;
            if (fmaf(sa[1], v0.y, sc[1]) > 0.f) w |= 2u;
            if (fmaf(sa[2], v0.z, sc[2]) > 0.f) w |= 4u;
            if (fmaf(sa[3], v0.w, sc[3]) > 0.f) w |= 8u;
            if (fmaf(sa[4], v1.x, sc[4]) > 0.f) w |= 16u;
            if (fmaf(sa[5], v1.y, sc[5]) > 0.f) w |= 32u;
            if (fmaf(sa[6], v1.z, sc[6]) > 0.f) w |= 64u;
            if (fmaf(sa[7], v1.w, sc[7]) > 0.f) w |= 128u;
            bufP32[e] = w;
        }
    }
    grid_sync();

    // ---- blocks 2..7 ----
    conv_phase<u32, 8, 12, 12, 12, 2, 5, 4, 2, 449, 111>(bufP32, g_bufM, g_wp2, g_scales + 0,   g_sS1 + 0,   g_sS2 + 0,   smu, gtid);
    grid_sync();
    pack_phase<u32, 12, 111>(g_bufM, bufP32, g_sS1 + 0,   g_sS2 + 0,   g_scales + 0,   g2, b2, 1.0 / (2048.0 * 111.0), smu, gtid);
    grid_sync();

    conv_phase<u32, 12, 32, 16, 9, 1, 4, 5, 2, 111, 54>(bufP32, g_bufM, g_wp3, g_scales + 12,  g_sS1 + 12,  g_sS2 + 12,  smu, gtid);
    grid_sync();
    pack_phase<u32, 32, 54>(g_bufM, bufP32, g_sS1 + 12,  g_sS2 + 12,  g_scales + 12,  g3, b3, 1.0 / (2048.0 * 54.0), smu, gtid);
    grid_sync();

    conv_phase<u32, 32, 64, 16, 7, 1, 3, 4, 2, 54, 26>(bufP32, g_bufM, g_wp4, g_scales + 44,  g_sS1 + 44,  g_sS2 + 44,  smu, gtid);
    grid_sync();
    pack_phase<u64, 64, 26>(g_bufM, g_bufP, g_sS1 + 44,  g_sS2 + 44,  g_scales + 44,  g4, b4, 1.0 / (2048.0 * 26.0), smu, gtid);
    grid_sync();

    conv_phase<u64, 64, 64, 16, 5, 1, 2, 2, 2, 26, 13>(g_bufP, g_bufM, g_wp5, g_scales + 108, g_sS1 + 108, g_sS2 + 108, smu, gtid);
    grid_sync();
    pack_phase<u64, 64, 13>(g_bufM, g_bufP, g_sS1 + 108, g_sS2 + 108, g_scales + 108, g5, b5, 1.0 / (2048.0 * 13.0), smu, gtid);
    grid_sync();

    conv_phase<u64, 64, 64, 16, 3, 1, 1, 2, 2, 13, 6>(g_bufP, g_bufM, g_wp6, g_scales + 172, g_sS1 + 172, g_sS2 + 172, smu, gtid);
    grid_sync();
    pack_phase<u64, 64, 6>(g_bufM, g_bufP, g_sS1 + 172, g_sS2 + 172, g_scales + 172, g6, b6, 1.0 / (2048.0 * 6.0), smu, gtid);
    grid_sync();

    conv_phase<u64, 64, 72, 24, 3, 1, 1, 2, 2, 6, 3>(g_bufP, g_bufM, g_wp7, g_scales + 236, g_sS1 + 236, g_sS2 + 236, smu, gtid);
    grid_sync();

    // ---- FC phase (block7 BN coefs recomputed per CTA) ----
    {
        float* sa = (float*)smu;
        float* sc = (float*)(smu + 40);
        if (tid < 72) {
            const double invcnt = 1.0 / (2048.0 * 3.0);
            double sl  = (double)(long long)g_sS1[236 + tid];
            double s2  = (double)(long long)g_sS2[236 + tid];
            double scw = (double)g_scales[236 + tid];
            double mm  = scw * sl * invcnt;
            double e2  = scw * scw * s2 * invcnt;
            double v   = e2 - mm * mm;
            if (v < 0.0) v = 0.0;
            double a = (double)g7[tid] / sqrt(v + 1e-5);
            sa[tid] = (float)a;
            sc[tid] = (float)((double)b7[tid] - mm * a);
        }
        __syncthreads();
        for (int e = gtid; e < NB * 5; e += TTOT) {
            const int n = e / 5, j = e - n * 5;
            const float* __restrict__ mb = g_bufM + (size_t)n * 216;   // [(n*3+l)*72+co]
            const float* __restrict__ wb = g_bwfc + j * 216;
            float s = 0.f;
#pragma unroll 4
            for (int co = 0; co < 72; co++) {
                float av = sa[co], cv = sc[co];
#pragma unroll
                for (int l = 0; l < 3; l++) {
                    float v = fmaf(av, mb[l * 72 + co], cv);
                    float sg = (v > 0.f) ? 1.f : ((v < 0.f) ? -1.f : 0.f);
                    s = fmaf(sg, __ldg(wb + co * 3 + l), s);
                }
            }
            out[e] = s;
        }
    }

    // restore barrier generation for graph replay (all CTAs passed the last barrier;
    // any late spinner compares against gen-1 and exits on either value)
    if (blockIdx.x == 0 && tid == 0) g_barGen = 0;
}

// ---------------- launch ----------------
extern "C" void kernel_launch(void* const* d_in, const int* in_sizes, int n_in,
                              void* d_out, int out_size)
{
    const float* x = (const float*)d_in[0];
    const float* w[7]; const float* g[7]; const float* b[7];
    const bool interleaved = (in_sizes[2] == 8);
    for (int i = 0; i < 7; i++) {
        if (interleaved) {
            w[i] = (const float*)d_in[1 + 3 * i];
            g[i] = (const float*)d_in[2 + 3 * i];
            b[i] = (const float*)d_in[3 + 3 * i];
        } else {
            w[i] = (const float*)d_in[1 + i];
            g[i] = (const float*)d_in[8 + i];
            b[i] = (const float*)d_in[15 + i];
        }
    }
    const float* wfc = (const float*)d_in[22];
    float* out = (float*)d_out;

    binw_all_kernel<<<321, 64>>>(w[0], w[1], w[2], w[3], w[4], w[5], w[6], wfc);
    mega_kernel<<<NCTA, NTHR>>>(x,
                                g[0], b[0], g[1], b[1], g[2], b[2], g[3], b[3],
                                g[4], b[4], g[5], b[5], g[6], b[6], out);
}

// round 7
// speedup vs baseline: 1.6252x; 1.6252x over previous
#include <cuda_runtime.h>
#include <math.h>

#define NB 2048

typedef unsigned int       u32;
typedef unsigned long long u64;

// ---------------- static device scratch ----------------
__device__ float  g_bufM[7356416];   // conv/pool outputs, layout [n][c][lp]
__device__ u64    g_bufP[919552];    // packed activations [n][lp]
__device__ float  g_bw1[128];
__device__ float  g_bwfc[1080];
__device__ u32    g_wp2[144];
__device__ u32    g_wp3[288];
__device__ u32    g_wp4[448];
__device__ u64    g_wp5[320];
__device__ u64    g_wp6[192];
__device__ u64    g_wp7[216];
__device__ float  g_scales[320];
__device__ double g_psd1[14400];     // block1 fp64 stat partials [8][1800]
__device__ double g_psd2[14400];
__device__ u64    g_sS1[320];        // exact int totals, layers 2-7
__device__ u64    g_sS2[320];
__device__ float  g_bna[16];
__device__ float  g_bnc[16];

__device__ __forceinline__ int popc_w(u32 x) { return __popc(x); }
__device__ __forceinline__ int popc_w(u64 x) { return __popcll(x); }
__device__ __forceinline__ u64 pack2f(float lo, float hi) {
    u64 d; asm("mov.b64 %0,{%1,%2};" : "=l"(d) : "f"(lo), "f"(hi)); return d;
}
__device__ __forceinline__ void unpack2f(u64 v, float& lo, float& hi) {
    asm("mov.b64 {%0,%1},%2;" : "=f"(lo), "=f"(hi) : "l"(v));
}
__device__ __forceinline__ u64 ffma2(u64 a, u64 b, u64 c) {
    u64 d; asm("fma.rn.f32x2 %0,%1,%2,%3;" : "=l"(d) : "l"(a), "l"(b), "l"(c)); return d;
}

// ---------------- weight binarization ----------------
__global__ void binw_all_kernel(
    const float* w1, const float* w2, const float* w3, const float* w4,
    const float* w5, const float* w6, const float* w7, const float* wfc)
{
    const int starts[9] = {0, 8, 20, 52, 116, 180, 244, 316, 321};
    const int CINs[8]   = {1, 8, 12, 32, 64, 64, 64, 216};
    const int Ks[8]     = {16, 12, 9, 7, 5, 3, 3, 1};
    const int soff[8]   = {0, 0, 12, 44, 108, 172, 236, 0};
    const float* ws[8]  = {w1, w2, w3, w4, w5, w6, w7, wfc};

    const int bx = blockIdx.x;
    int layer = 0;
    while (bx >= starts[layer + 1]) layer++;
    const int o   = bx - starts[layer];
    const int CIN = CINs[layer], K = Ks[layer], IK = CIN * K;
    const float* wrow = ws[layer] + o * IK;
    const int tid = threadIdx.x;

    __shared__ double sd[64];
    double acc = 0.0;
    for (int i = tid; i < IK; i += 64) acc += (double)fabsf(wrow[i]);
    sd[tid] = acc;
    __syncthreads();
    for (int s = 32; s > 0; s >>= 1) {
        if (tid < s) sd[tid] += sd[tid + s];
        __syncthreads();
    }
    const float scale = (float)(sd[0] / (double)IK);

    if (layer == 0) {
        for (int i = tid; i < IK; i += 64) {
            float v = wrow[i];
            g_bw1[o * IK + i] = (v > 0.f) ? scale : ((v < 0.f) ? -scale : 0.f);
        }
    } else if (layer == 7) {
        for (int i = tid; i < IK; i += 64) {
            float v = wrow[i];
            g_bwfc[o * IK + i] = (v > 0.f) ? scale : ((v < 0.f) ? -scale : 0.f);
        }
    } else {
        if (tid == 0) g_scales[soff[layer] + o] = scale;
        if (layer <= 3) {
            u32* wp = (layer == 1) ? g_wp2 : (layer == 2) ? g_wp3 : g_wp4;
            for (int k = tid; k < K; k += 64) {
                u32 word = 0;
                for (int ci = 0; ci < CIN; ci++)
                    if (wrow[ci * K + k] > 0.f) word |= (1u << ci);
                wp[o * K + k] = word;
            }
        } else {
            u64* wp = (layer == 4) ? g_wp5 : (layer == 5) ? g_wp6 : g_wp7;
            for (int k = tid; k < K; k += 64) {
                u64 word = 0;
                for (int ci = 0; ci < CIN; ci++)
                    if (wrow[ci * K + k] > 0.f) word |= (1ull << ci);
                wp[o * K + k] = word;
            }
        }
    }
}

// =============== block 1: fp32 conv + maxpool via FFMA2, 2 pool outputs/thread ===============
__global__ void __launch_bounds__(256) conv1_kernel(
    const float* __restrict__ x, float* __restrict__ out,
    double* __restrict__ ps1, double* __restrict__ ps2)
{
    constexpr int LIN = 3600, LP = 449, CO = 8;
    __shared__ u64 sw2[128];
    const int tid = threadIdx.x;
    if (tid < 128) { float w = g_bw1[tid]; sw2[tid] = pack2f(w, w); }
    __syncthreads();

    const int idx  = blockIdx.x * 256 + tid;      // < 2048*225 exact
    const int n    = idx / 225;
    const int slot = idx - n * 225;
    const int lp0  = slot * 2;
    const bool v1  = (slot < 224);
    const int base0 = lp0 * 8 - 7;
    const float* __restrict__ xp = x + (size_t)n * LIN;

    float win[38];
#pragma unroll
    for (int t = 0; t < 38; t++) {
        int p = base0 + t;
        win[t] = (p >= 0 && p < LIN) ? xp[p] : 0.f;
    }
    u64 pz[36];
#pragma unroll
    for (int t = 0; t < 36; t++) pz[t] = pack2f(win[t], win[t + 2]);

    __shared__ float sh1[8][CO], sh2[8][CO];
    const int lane = tid & 31, wid = tid >> 5;

#pragma unroll
    for (int c = 0; c < CO; c++) {
        u64 a0 = 0, a1 = 0, a2 = 0, a3 = 0, a4 = 0, a5 = 0;
#pragma unroll
        for (int k = 0; k < 16; k++) {
            u64 wk = sw2[c * 16 + k];
            a0 = ffma2(pz[k],      wk, a0);
            a1 = ffma2(pz[4 + k],  wk, a1);
            a2 = ffma2(pz[8 + k],  wk, a2);
            a3 = ffma2(pz[12 + k], wk, a3);
            a4 = ffma2(pz[16 + k], wk, a4);
            a5 = ffma2(pz[20 + k], wk, a5);
        }
        float s0, s1, s2v, s3, s4, s5, s6, s7, s8, s9, s10, s11;
        unpack2f(a0, s0, s1);  unpack2f(a1, s2v, s3); unpack2f(a2, s4, s5);
        unpack2f(a3, s6, s7);  unpack2f(a4, s8, s9);  unpack2f(a5, s10, s11);
        float m0 = fmaxf(fmaxf(fmaxf(s0, s1), fmaxf(s2v, s3)),
                         fmaxf(fmaxf(s4, s5), fmaxf(s6, s7)));
        float m1 = fmaxf(fmaxf(fmaxf(s4, s5), fmaxf(s6, s7)),
                         fmaxf(fmaxf(s8, s9), fmaxf(s10, s11)));
        out[((size_t)n * CO + c) * LP + lp0] = m0;
        if (v1) out[((size_t)n * CO + c) * LP + lp0 + 1] = m1;

        float f1 = m0 + (v1 ? m1 : 0.f);
        float f2 = m0 * m0 + (v1 ? m1 * m1 : 0.f);
#pragma unroll
        for (int off = 16; off > 0; off >>= 1) {
            f1 += __shfl_down_sync(0xFFFFFFFFu, f1, off);
            f2 += __shfl_down_sync(0xFFFFFFFFu, f2, off);
        }
        if (lane == 0) { sh1[wid][c] = f1; sh2[wid][c] = f2; }
    }
    __syncthreads();
    if (tid < CO) {
        double t1 = 0.0, t2 = 0.0;
#pragma unroll
        for (int q = 0; q < 8; q++) { t1 += (double)sh1[q][tid]; t2 += (double)sh2[q][tid]; }
        ps1[tid * 1800 + blockIdx.x] = t1;
        ps2[tid * 1800 + blockIdx.x] = t2;
    }
}

// =============== block1 BN finalize ===============
__global__ void stats_fin_d(const double* __restrict__ ps1, const double* __restrict__ ps2,
                            const float* __restrict__ gamma, const float* __restrict__ beta,
                            float* __restrict__ bna, float* __restrict__ bnc)
{
    const int ch = blockIdx.x, G = 1800;
    __shared__ double s1[256], s2[256];
    double a1 = 0.0, a2 = 0.0;
    for (int i = threadIdx.x; i < G; i += 256) { a1 += ps1[ch * G + i]; a2 += ps2[ch * G + i]; }
    s1[threadIdx.x] = a1; s2[threadIdx.x] = a2;
    __syncthreads();
    for (int s = 128; s > 0; s >>= 1) {
        if (threadIdx.x < s) { s1[threadIdx.x] += s1[threadIdx.x + s]; s2[threadIdx.x] += s2[threadIdx.x + s]; }
        __syncthreads();
    }
    if (threadIdx.x == 0) {
        const double invcnt = 1.0 / (2048.0 * 449.0);
        double m = s1[0] * invcnt;
        double v = s2[0] * invcnt - m * m;
        if (v < 0.0) v = 0.0;
        double a = (double)gamma[ch] / sqrt(v + 1e-5);
        bna[ch] = (float)a;
        bnc[ch] = (float)((double)beta[ch] - m * a);
    }
}

// =============== warp-cooperative XNOR conv+pool (L2-L4, u32, PS=2) ===============
// Each lane computes PS conv positions; pool maxes assembled via shfl_down.
template <int CIN, int COUT, int CB, int K, int STR, int PAD, int PK, int PS,
          int LIN, int LP, int LC, int WPI>
__global__ void __launch_bounds__(256) conv_popc_warp(
    const u32* __restrict__ inP, float* __restrict__ out,
    const u32* __restrict__ wp, const float* __restrict__ scales,
    u64* __restrict__ sT1, u64* __restrict__ sT2)
{
    constexpr int OPW   = (PK == 5) ? 30 : 31;       // outputs per warp
    constexpr int WREAL = (PS - 1) * STR + K;
    constexpr int IPC   = 8 / WPI;                   // images per CTA
    constexpr u32 MCIN  = (CIN >= 32) ? 0xFFFFFFFFu : ((1u << CIN) - 1u);

    __shared__ u32   sw[COUT * K];
    __shared__ float ssc[COUT];
    __shared__ int   ssum[COUT], ssq[COUT];
    const int tid = threadIdx.x;
    for (int i = tid; i < COUT * K; i += 256) sw[i] = wp[i];
    if (tid < COUT) { ssc[tid] = scales[tid]; ssum[tid] = 0; ssq[tid] = 0; }
    __syncthreads();

    const int lane = tid & 31, warp = tid >> 5;
    const int n     = blockIdx.x * IPC + warp / WPI;
    const int chunk = warp % WPI;
    const int lp    = chunk * OPW + lane;
    const int p0    = lp * PS;
    const int base  = p0 * STR - PAD;
    const u32* __restrict__ ib = inP + (size_t)n * LIN;

    u32 win[WREAL], msk[WREAL];
#pragma unroll
    for (int t = 0; t < WREAL; t++) {
        int p = base + t;
        bool v = (p >= 0 && p < LIN);
        win[t] = v ? ib[p] : 0u;
        msk[t] = v ? MCIN : 0u;
    }
    int cnt[PS];
    bool posv[PS];
#pragma unroll
    for (int d = 0; d < PS; d++) {
        posv[d] = (p0 + d) < LC;
        int cc = 0;
#pragma unroll
        for (int k = 0; k < K; k++) cc += (msk[d * STR + k] != 0) ? CIN : 0;
        cnt[d] = cc;
    }
    const bool outv = (lane < OPW) && (lp < LP);

#pragma unroll 1
    for (int cb = 0; cb < COUT; cb += CB) {
        int P[CB][PS];
#pragma unroll
        for (int c = 0; c < CB; c++)
#pragma unroll
            for (int d = 0; d < PS; d++) P[c][d] = 0;
#pragma unroll
        for (int k = 0; k < K; k++) {
#pragma unroll
            for (int c = 0; c < CB; c++) {
                u32 wk = sw[(cb + c) * K + k];
#pragma unroll
                for (int d = 0; d < PS; d++) {
                    int t = d * STR + k;
                    P[c][d] += __popc(~(win[t] ^ wk) & msk[t]);
                }
            }
        }
#pragma unroll
        for (int c = 0; c < CB; c++) {
            int s0 = posv[0] ? (2 * P[c][0] - cnt[0]) : (-(1 << 30));
            int s1 = posv[1] ? (2 * P[c][1] - cnt[1]) : (-(1 << 30));
            int pmax = (s0 > s1) ? s0 : s1;
            int pm1 = __shfl_down_sync(0xFFFFFFFFu, pmax, 1);
            int m = (pmax > pm1) ? pmax : pm1;
            if (PK == 5) {
                int s02 = __shfl_down_sync(0xFFFFFFFFu, s0, 2);
                m = (m > s02) ? m : s02;
            }
            if (outv) out[((size_t)n * COUT + cb + c) * LP + lp] = ssc[cb + c] * (float)m;
            int mm  = outv ? m : 0;
            int mm2 = outv ? m * m : 0;
            int r1 = __reduce_add_sync(0xFFFFFFFFu, mm);
            int r2 = __reduce_add_sync(0xFFFFFFFFu, mm2);
            if (lane == 0) { atomicAdd(&ssum[cb + c], r1); atomicAdd(&ssq[cb + c], r2); }
        }
    }
    __syncthreads();
    if (tid < COUT) {
        atomicAdd(&sT1[tid], (u64)(long long)ssum[tid]);
        atomicAdd(&sT2[tid], (u64)(long long)ssq[tid]);
    }
}

// =============== XNOR-popcount conv (L5-L7, u64, PK=PS -> no sharing) ===============
template <typename WT, int CIN, int COUT, int CO_T, int K, int STR, int PAD, int PK, int PS, int LIN, int LP>
__global__ void __launch_bounds__(256) conv_popc_kernel(
    const WT* __restrict__ inP, float* __restrict__ out,
    const WT* __restrict__ wp, const float* __restrict__ scales,
    u64* __restrict__ sS1, u64* __restrict__ sS2)
{
    constexpr int WREAL = (PK - 1) * STR + K;
    constexpr WT  MCIN  = (CIN >= (int)(8 * sizeof(WT))) ? (WT)~(WT)0 : (WT)(((WT)1 << CIN) - 1);

    __shared__ WT sw[CO_T * K];
    __shared__ float ssc[CO_T];
    __shared__ int ssum[CO_T], ssq[CO_T];
    const int cob = blockIdx.y * CO_T;
    const int tid = threadIdx.x;
    for (int i = tid; i < CO_T * K; i += 256) sw[i] = wp[cob * K + i];
    if (tid < CO_T) { ssc[tid] = scales[cob + tid]; ssum[tid] = 0; ssq[tid] = 0; }
    __syncthreads();

    const int idx = blockIdx.x * 256 + tid;          // exact grid
    const int n = idx / LP, lp = idx - n * LP;
    const int base0 = lp * PS * STR - PAD;
    const WT* __restrict__ ib = inP + (size_t)n * LIN;

    WT win[WREAL], msk[WREAL];
    int cnt[PK];
#pragma unroll
    for (int t = 0; t < WREAL; t++) {
        int p = base0 + t;
        bool v = (p >= 0 && p < LIN);
        win[t] = v ? ib[p] : (WT)0;
        msk[t] = v ? MCIN : (WT)0;
    }
#pragma unroll
    for (int j = 0; j < PK; j++) {
        int cc = 0;
#pragma unroll
        for (int k = 0; k < K; k++) cc += (msk[j * STR + k] != 0) ? CIN : 0;
        cnt[j] = cc;
    }

    int P[CO_T][PK];
#pragma unroll
    for (int c = 0; c < CO_T; c++)
#pragma unroll
        for (int j = 0; j < PK; j++) P[c][j] = 0;

#pragma unroll
    for (int k = 0; k < K; k++) {
#pragma unroll
        for (int c = 0; c < CO_T; c++) {
            WT wk = sw[c * K + k];
#pragma unroll
            for (int j = 0; j < PK; j++) {
                int t = j * STR + k;
                P[c][j] += popc_w((WT)(~(win[t] ^ wk) & msk[t]));
            }
        }
    }

    const int lane = tid & 31;
#pragma unroll
    for (int c = 0; c < CO_T; c++) {
        int m = 2 * P[c][0] - cnt[0];
#pragma unroll
        for (int j = 1; j < PK; j++) {
            int s = 2 * P[c][j] - cnt[j];
            m = (s > m) ? s : m;
        }
        out[((size_t)n * COUT + cob + c) * LP + lp] = ssc[c] * (float)m;
        int r1 = __reduce_add_sync(0xFFFFFFFFu, m);
        int r2 = __reduce_add_sync(0xFFFFFFFFu, m * m);
        if (lane == 0) { atomicAdd(&ssum[c], r1); atomicAdd(&ssq[c], r2); }
    }
    __syncthreads();
    if (tid < CO_T) {
        atomicAdd(&sS1[cob + tid], (u64)(long long)ssum[tid]);
        atomicAdd(&sS2[cob + tid], (u64)(long long)ssq[tid]);
    }
}

// =============== pack for block1 + zero next-layer slots ===============
__global__ void __launch_bounds__(256) pack1_kernel(
    const float* __restrict__ m, const float* __restrict__ a, const float* __restrict__ c,
    u32* __restrict__ outP, u64* __restrict__ z1, u64* __restrict__ z2)
{
    constexpr int C = 8, LP = 449;
    __shared__ float sa[C], sc[C];
    if (threadIdx.x < C) { sa[threadIdx.x] = a[threadIdx.x]; sc[threadIdx.x] = c[threadIdx.x]; }
    if (blockIdx.x == 0 && threadIdx.x < 12) { z1[threadIdx.x] = 0; z2[threadIdx.x] = 0; }
    __syncthreads();
    const int idx = blockIdx.x * 256 + threadIdx.x;
    const int n = idx / LP, lp = idx - n * LP;
    u32 word = 0;
#pragma unroll
    for (int co = 0; co < C; co++) {
        float v = fmaf(sa[co], m[((size_t)n * C + co) * LP + lp], sc[co]);
        if (v > 0.f) word |= (1u << co);
    }
    outP[(size_t)n * LP + lp] = word;
}

// =============== pack with in-CTA BN recompute + zero next slots ===============
template <typename WT, int C, int LP>
__global__ void __launch_bounds__(256) pack_stats_kernel(
    const float* __restrict__ m,
    const u64* __restrict__ sS1, const u64* __restrict__ sS2,
    const float* __restrict__ scales,
    const float* __restrict__ gamma, const float* __restrict__ beta,
    double invcnt, WT* __restrict__ outP,
    u64* __restrict__ z1, u64* __restrict__ z2, int zcnt)
{
    __shared__ float sa[C], sc[C];
    if (threadIdx.x < C) {
        const int ch = threadIdx.x;
        double sl = (double)(long long)sS1[ch];
        double s2 = (double)(long long)sS2[ch];
        double scw = (double)scales[ch];
        double mm = scw * sl * invcnt;
        double e2 = scw * scw * s2 * invcnt;
        double v  = e2 - mm * mm;
        if (v < 0.0) v = 0.0;
        double a = (double)gamma[ch] / sqrt(v + 1e-5);
        sa[ch] = (float)a;
        sc[ch] = (float)((double)beta[ch] - mm * a);
    }
    if (blockIdx.x == 0 && threadIdx.x < zcnt) { z1[threadIdx.x] = 0; z2[threadIdx.x] = 0; }
    __syncthreads();
    const int idx = blockIdx.x * 256 + threadIdx.x;   // exact grid
    const int n = idx / LP, lp = idx - n * LP;
    WT word = 0;
#pragma unroll
    for (int co = 0; co < C; co++) {
        float v = fmaf(sa[co], m[((size_t)n * C + co) * LP + lp], sc[co]);
        if (v > 0.f) word |= ((WT)1 << co);
    }
    outP[(size_t)n * LP + lp] = word;
}

// =============== FC with in-CTA block7 BN recompute ===============
__global__ void fc_bn_kernel(const float* __restrict__ m7, const float* __restrict__ bwfc,
                             const u64* __restrict__ sS1, const u64* __restrict__ sS2,
                             const float* __restrict__ scales,
                             const float* __restrict__ gamma, const float* __restrict__ beta,
                             float* __restrict__ out)
{
    __shared__ float sa[72], sc[72];
    const int tid = threadIdx.x;
    if (tid < 72) {
        const double invcnt = 1.0 / (2048.0 * 3.0);
        double sl = (double)(long long)sS1[tid];
        double s2 = (double)(long long)sS2[tid];
        double scw = (double)scales[tid];
        double mm = scw * sl * invcnt;
        double e2 = scw * scw * s2 * invcnt;
        double v  = e2 - mm * mm;
        if (v < 0.0) v = 0.0;
        double a = (double)gamma[tid] / sqrt(v + 1e-5);
        sa[tid] = (float)a;
        sc[tid] = (float)((double)beta[tid] - mm * a);
    }
    __syncthreads();

    const int idx = blockIdx.x * 256 + tid;
    if (idx >= NB * 5) return;
    const int n = idx / 5, j = idx - n * 5;
    const float* __restrict__ mb = m7 + (size_t)n * 216;   // layout [n][c][lp], lp=3
    const float* __restrict__ wb = bwfc + j * 216;
    float s = 0.f;
#pragma unroll 4
    for (int co = 0; co < 72; co++) {
        float av = sa[co], cv = sc[co];
#pragma unroll
        for (int l = 0; l < 3; l++) {
            float v = fmaf(av, mb[co * 3 + l], cv);
            float sg = (v > 0.f) ? 1.f : ((v < 0.f) ? -1.f : 0.f);
            s = fmaf(sg, wb[co * 3 + l], s);
        }
    }
    out[n * 5 + j] = s;
}

// ---------------- launch ----------------
extern "C" void kernel_launch(void* const* d_in, const int* in_sizes, int n_in,
                              void* d_out, int out_size)
{
    const float* x = (const float*)d_in[0];
    const float* w[7]; const float* g[7]; const float* b[7];
    const bool interleaved = (in_sizes[2] == 8);
    for (int i = 0; i < 7; i++) {
        if (interleaved) {
            w[i] = (const float*)d_in[1 + 3 * i];
            g[i] = (const float*)d_in[2 + 3 * i];
            b[i] = (const float*)d_in[3 + 3 * i];
        } else {
            w[i] = (const float*)d_in[1 + i];
            g[i] = (const float*)d_in[8 + i];
            b[i] = (const float*)d_in[15 + i];
        }
    }
    const float* wfc = (const float*)d_in[22];
    float* out = (float*)d_out;

    float *bufM, *bwfc, *scales, *bna, *bnc;
    u64 *bufP, *wp5, *wp6, *wp7, *sS1, *sS2;
    u32 *wp2, *wp3, *wp4;
    double *psd1, *psd2;
    cudaGetSymbolAddress((void**)&bufM, g_bufM);
    cudaGetSymbolAddress((void**)&bufP, g_bufP);
    cudaGetSymbolAddress((void**)&bwfc, g_bwfc);
    cudaGetSymbolAddress((void**)&wp2, g_wp2);
    cudaGetSymbolAddress((void**)&wp3, g_wp3);
    cudaGetSymbolAddress((void**)&wp4, g_wp4);
    cudaGetSymbolAddress((void**)&wp5, g_wp5);
    cudaGetSymbolAddress((void**)&wp6, g_wp6);
    cudaGetSymbolAddress((void**)&wp7, g_wp7);
    cudaGetSymbolAddress((void**)&scales, g_scales);
    cudaGetSymbolAddress((void**)&psd1, g_psd1);
    cudaGetSymbolAddress((void**)&psd2, g_psd2);
    cudaGetSymbolAddress((void**)&sS1, g_sS1);
    cudaGetSymbolAddress((void**)&sS2, g_sS2);
    cudaGetSymbolAddress((void**)&bna, g_bna);
    cudaGetSymbolAddress((void**)&bnc, g_bnc);

    u32* bufP32 = (u32*)bufP;

    binw_all_kernel<<<321, 64>>>(w[0], w[1], w[2], w[3], w[4], w[5], w[6], wfc);

    // block 1
    conv1_kernel<<<1800, 256>>>(x, bufM, psd1, psd2);
    stats_fin_d<<<8, 256>>>(psd1, psd2, g[0], b[0], bna, bnc);
    pack1_kernel<<<3592, 256>>>(bufM, bna, bnc, bufP32, sS1 + 0, sS2 + 0);

    // block 2: 8->12, k12 s2 p5, pool 4/2, 449->111  (LC=224, WPI=4)
    conv_popc_warp<8, 12, 12, 12, 2, 5, 4, 2, 449, 111, 224, 4>
        <<<1024, 256>>>(bufP32, bufM, wp2, scales + 0, sS1 + 0, sS2 + 0);
    pack_stats_kernel<u32, 12, 111><<<888, 256>>>(bufM, sS1 + 0, sS2 + 0, scales + 0,
        g[1], b[1], 1.0 / (2048.0 * 111.0), bufP32, sS1 + 12, sS2 + 12, 32);

    // block 3: 12->32, k9 s1 p4, pool 5/2, 111->54  (LC=111, WPI=2)
    conv_popc_warp<12, 32, 16, 9, 1, 4, 5, 2, 111, 54, 111, 2>
        <<<512, 256>>>(bufP32, bufM, wp3, scales + 12, sS1 + 12, sS2 + 12);
    pack_stats_kernel<u32, 32, 54><<<432, 256>>>(bufM, sS1 + 12, sS2 + 12, scales + 12,
        g[2], b[2], 1.0 / (2048.0 * 54.0), bufP32, sS1 + 44, sS2 + 44, 64);

    // block 4: 32->64, k7 s1 p3, pool 4/2, 54->26  (LC=54, WPI=1)
    conv_popc_warp<32, 64, 16, 7, 1, 3, 4, 2, 54, 26, 54, 1>
        <<<256, 256>>>(bufP32, bufM, wp4, scales + 44, sS1 + 44, sS2 + 44);
    pack_stats_kernel<u64, 64, 26><<<208, 256>>>(bufM, sS1 + 44, sS2 + 44, scales + 44,
        g[3], b[3], 1.0 / (2048.0 * 26.0), bufP, sS1 + 108, sS2 + 108, 64);

    // block 5: 64->64, k5 s1 p2, pool 2/2, 26->13
    conv_popc_kernel<u64, 64, 64, 16, 5, 1, 2, 2, 2, 26, 13>
        <<<dim3(104, 4), 256>>>(bufP, bufM, wp5, scales + 108, sS1 + 108, sS2 + 108);
    pack_stats_kernel<u64, 64, 13><<<104, 256>>>(bufM, sS1 + 108, sS2 + 108, scales + 108,
        g[4], b[4], 1.0 / (2048.0 * 13.0), bufP, sS1 + 172, sS2 + 172, 64);

    // block 6: 64->64, k3 s1 p1, pool 2/2, 13->6
    conv_popc_kernel<u64, 64, 64, 16, 3, 1, 1, 2, 2, 13, 6>
        <<<dim3(48, 4), 256>>>(bufP, bufM, wp6, scales + 172, sS1 + 172, sS2 + 172);
    pack_stats_kernel<u64, 64, 6><<<48, 256>>>(bufM, sS1 + 172, sS2 + 172, scales + 172,
        g[5], b[5], 1.0 / (2048.0 * 6.0), bufP, sS1 + 236, sS2 + 236, 72);

    // block 7: 64->72, k3 s1 p1, pool 2/2, 6->3
    conv_popc_kernel<u64, 64, 72, 24, 3, 1, 1, 2, 2, 6, 3>
        <<<dim3(24, 3), 256>>>(bufP, bufM, wp7, scales + 236, sS1 + 236, sS2 + 236);

    // FC
    fc_bn_kernel<<<(NB * 5 + 255) / 256, 256>>>(bufM, bwfc, sS1 + 236, sS2 + 236,
                                                scales + 236, g[6], b[6], out);
}